// round 3
// baseline (speedup 1.0000x reference)
#include <cuda_runtime.h>
#include <stdint.h>

// Hash-grid trilinear interpolation — warp-cooperative gather version.
//
// Layout trick: P1 = 1, so corner pairs (2p, 2p+1) occupy ADJACENT buckets
// -> 64 contiguous bytes of features. 4 lanes load that 64B in one LDG.128
// instruction, merging into ~1-2 L1tex wavefronts (vs 4 random ones).
// 16 lanes = one point (4 pairs x 4 float4), warp = 2 points per round.
// Reduction: shfl.xor over masks {2,4,8}; lane0 = lo half, lane1 = hi half.
//
// Cache policy: gathers evict_last via createpolicy+cache_hint (keep 128MB
// table resident in ~126MB L2); pts / out streaming (evict-first-ish) so
// they don't evict the table.

#define BUCKETS_MASK ((1u << 22) - 1u)
#define P1 1u
#define P2 2654435761u
#define P3 805459861u

__device__ __forceinline__ uint64_t mk_policy_evict_last() {
    uint64_t pol;
    asm("createpolicy.fractional.L2::evict_last.b64 %0, 1.0;" : "=l"(pol));
    return pol;
}

__device__ __forceinline__ float4 ldg_hint(const void* p, uint64_t pol) {
    float4 v;
    asm("ld.global.nc.L2::cache_hint.v4.f32 {%0,%1,%2,%3}, [%4], %5;"
        : "=f"(v.x), "=f"(v.y), "=f"(v.z), "=f"(v.w)
        : "l"(p), "l"(pol));
    return v;
}

template <int U>
__global__ void __launch_bounds__(256) hashgrid_coop_kernel(
    const float* __restrict__ pts,   // (N,3)
    const char*  __restrict__ vf,    // (BUCKETS, 8 fp32) = 32 B per bucket
    float4*      __restrict__ out,   // (N, 8 fp32) = 2 float4 per point
    int n)
{
    int warp_g = (blockIdx.x * blockDim.x + threadIdx.x) >> 5;
    int lane   = threadIdx.x & 31;
    int l      = lane & 15;          // lane within 16-lane point-group
    int group  = lane >> 4;          // which of the warp's 2 points this round

    int pair = l >> 2;               // corner pair 0..3
    int j    = l & 3;                // float4 slot within the 64B pair block
    int c    = 2 * pair + (j >> 1);  // corner index 0..7
    uint32_t cx = (uint32_t)(c & 1);
    uint32_t cy = (uint32_t)((c >> 1) & 1);
    uint32_t cz = (uint32_t)((c >> 2) & 1);
    // additive hash offset for this lane's corner
    uint32_t hoff = cx * P1 + cy * P2 + cz * P3;

    uint64_t pol = mk_policy_evict_last();

    int base = warp_g * (2 * U);

    float4 f[U];
    float  wgt[U];
    int    idx[U];
    bool   valid[U];

#pragma unroll
    for (int r = 0; r < U; r++) {
        int i = base + 2 * r + group;
        idx[r]   = i;
        valid[r] = (i < n);
        int ii = valid[r] ? i : 0;

        // broadcast load of the point (16 lanes same addr -> merged wavefront)
        float x = __ldcs(pts + 3 * ii + 0);
        float y = __ldcs(pts + 3 * ii + 1);
        float z = __ldcs(pts + 3 * ii + 2);

        float qx = x * 1024.0f, qy = y * 1024.0f, qz = z * 1024.0f;
        float bxf = floorf(qx), byf = floorf(qy), bzf = floorf(qz);
        float fx = qx - bxf, fy = qy - byf, fz = qz - bzf;

        uint32_t bx = (uint32_t)(int)bxf;
        uint32_t by = (uint32_t)(int)byf;
        uint32_t bz = (uint32_t)(int)bzf;
        uint32_t h  = bx * P1 + by * P2 + bz * P3;

        uint32_t vid = (h + hoff) & BUCKETS_MASK;
        const char* ptr = vf + ((size_t)vid << 5) + ((uint32_t)(j & 1) << 4);
        f[r] = ldg_hint(ptr, pol);         // issued early, U in flight per lane

        float wx = cx ? fx : 1.0f - fx;
        float wy = cy ? fy : 1.0f - fy;
        float wz = cz ? fz : 1.0f - fz;
        wgt[r] = wx * wy * wz;
    }

#pragma unroll
    for (int r = 0; r < U; r++) {
        float4 v;
        v.x = wgt[r] * f[r].x;
        v.y = wgt[r] * f[r].y;
        v.z = wgt[r] * f[r].z;
        v.w = wgt[r] * f[r].w;

        // butterfly sum over 8 lanes of same j-parity
#pragma unroll
        for (int m = 2; m <= 8; m <<= 1) {
            v.x += __shfl_xor_sync(0xFFFFFFFFu, v.x, m);
            v.y += __shfl_xor_sync(0xFFFFFFFFu, v.y, m);
            v.z += __shfl_xor_sync(0xFFFFFFFFu, v.z, m);
            v.w += __shfl_xor_sync(0xFFFFFFFFu, v.w, m);
        }

        // lane 0 has out_lo, lane 1 has out_hi (per group); 4 stores/warp = 64B line
        if (l < 2 && valid[r]) {
            __stcs(out + 2 * (size_t)idx[r] + l, v);
        }
    }
}

extern "C" void kernel_launch(void* const* d_in, const int* in_sizes, int n_in,
                              void* d_out, int out_size)
{
    const float* pts = (const float*)d_in[0];
    const char*  vf  = (const char*)d_in[1];
    float4*      out = (float4*)d_out;

    int n = in_sizes[0] / 3;

    constexpr int U = 4;                 // points-per-warp = 2*U = 8
    long long warps   = ((long long)n + (2 * U) - 1) / (2 * U);
    long long threads = warps * 32;
    int block = 256;
    long long grid = (threads + block - 1) / block;

    hashgrid_coop_kernel<U><<<(int)grid, block>>>(pts, vf, out, n);
}